// round 6
// baseline (speedup 1.0000x reference)
#include <cuda_runtime.h>
#include <math.h>

#define Bsz  2
#define Nseq 2048
#define Emb  1024
#define Hh   16
#define Dh   64

// Scratch (allocation-free: __device__ globals)
__device__ float g_q [Bsz * Hh * Nseq * Dh];   // [B,H,N,D] (tf32-rounded)
__device__ float g_k [Bsz * Hh * Nseq * Dh];
__device__ float g_v [Bsz * Hh * Nseq * Dh];
__device__ float g_ao[Bsz * Nseq * Hh * Dh];   // [B,N,H*D] (tf32-rounded)
__device__ float g_x [Bsz * Nseq * Emb];       // tf32-rounded x
__device__ float g_wq[3 * Hh * Dh * Emb];      // tf32-rounded Wqkv
__device__ float g_wo[Emb * Hh * Dh];          // tf32-rounded Wout

// ---------------------------------------------------------------------------
// helpers
// ---------------------------------------------------------------------------
__device__ __forceinline__ float f2tf32(float f) {
    unsigned r;
    asm("cvt.rna.tf32.f32 %0, %1;" : "=r"(r) : "f"(f));
    return __uint_as_float(r);
}

__device__ __forceinline__ void mma_tf32(float* c, const unsigned* a, const unsigned* b) {
    asm volatile(
        "mma.sync.aligned.m16n8k8.row.col.f32.tf32.tf32.f32 "
        "{%0,%1,%2,%3},{%4,%5,%6,%7},{%8,%9},{%0,%1,%2,%3};"
        : "+f"(c[0]), "+f"(c[1]), "+f"(c[2]), "+f"(c[3])
        : "r"(a[0]), "r"(a[1]), "r"(a[2]), "r"(a[3]), "r"(b[0]), "r"(b[1]));
}

__device__ __forceinline__ void ldsm_x4(unsigned& r0, unsigned& r1, unsigned& r2, unsigned& r3,
                                        unsigned saddr) {
    asm volatile("ldmatrix.sync.aligned.m8n8.x4.shared.b16 {%0,%1,%2,%3}, [%4];"
                 : "=r"(r0), "=r"(r1), "=r"(r2), "=r"(r3) : "r"(saddr));
}

__device__ __forceinline__ void cp16(void* dst_smem, const void* src_gmem) {
    unsigned d = (unsigned)__cvta_generic_to_shared(dst_smem);
    asm volatile("cp.async.cg.shared.global [%0], [%1], 16;" :: "r"(d), "l"(src_gmem));
}

// ---------------------------------------------------------------------------
// tf32 pre-convert pass
// ---------------------------------------------------------------------------
__global__ void cvt_tf32_kernel(const float4* __restrict__ in, float4* __restrict__ out, int n4)
{
    const int i = blockIdx.x * 256 + threadIdx.x;
    if (i < n4) {
        float4 v = in[i];
        float4 r;
        r.x = f2tf32(v.x); r.y = f2tf32(v.y); r.z = f2tf32(v.z); r.w = f2tf32(v.w);
        out[i] = r;
    }
}

// ---------------------------------------------------------------------------
// TF32 GEMM: C[r][c] = sum_k A[r][k] * W[c][k] + bias[c]
// 128x128 block tile, BK=32, 128 threads = 4 warps (2 x 2), warp tile 64x64.
// 3-stage cp.async pipeline, 128B-swizzled smem, ldmatrix fragment loads.
// Dynamic smem: 3 stages x (4096 + 4096) floats = 96 KB.
// ---------------------------------------------------------------------------
template <int MODE>
__global__ void __launch_bounds__(128, 2) gemm_tf32_kernel(const float* __restrict__ bias,
                                                           float* __restrict__ out)
{
    extern __shared__ float smem[];
    float* Asm = smem;           // 3 stages x 4096 floats
    float* Wsm = smem + 12288;   // 3 stages x 4096 floats

    const float* Ain = (MODE == 0) ? g_x  : g_ao;
    const float* Win = (MODE == 0) ? g_wq : g_wo;

    const int tid  = threadIdx.x;
    const int lane = tid & 31;
    const int warp = tid >> 5;
    const int wm   = warp & 1;         // 0..1 : 64-row group
    const int wn   = warp >> 1;        // 0..1 : 64-col group
    const int bm = blockIdx.y * 128;
    const int bn = blockIdx.x * 128;

    const int gid = lane >> 2;
    const int tig = lane & 3;

    // ldmatrix per-lane address components
    const int a_row  = lane & 15;
    const int a_cbit = lane >> 4;
    const int b_row  = (lane & 7) + ((lane & 16) >> 1);
    const int b_cbit = (lane >> 3) & 1;

    float acc[4][8][4];
#pragma unroll
    for (int mi = 0; mi < 4; mi++)
#pragma unroll
        for (int nj = 0; nj < 8; nj++)
#pragma unroll
            for (int q = 0; q < 4; q++) acc[mi][nj][q] = 0.f;

    auto cp_tile = [&](int kt, int stage) {
        const float* Ab = Ain + (size_t)bm * Emb + kt * 32;
        const float* Wb = Win + (size_t)bn * Emb + kt * 32;
        float* as = Asm + stage * 4096;
        float* ws = Wsm + stage * 4096;
#pragma unroll
        for (int i = 0; i < 8; i++) {
            const int idx = tid + i * 128;          // 0..1023
            const int row = idx >> 3;               // 0..127
            const int ch  = idx & 7;                // 16B chunk
            const int off = row * 32 + ((ch ^ (row & 7)) << 2);
            cp16(as + off, Ab + (size_t)row * Emb + ch * 4);
            cp16(ws + off, Wb + (size_t)row * Emb + ch * 4);
        }
        asm volatile("cp.async.commit_group;");
    };

    const int NT = Emb / 32;
    cp_tile(0, 0);
    cp_tile(1, 1);

    for (int kt = 0; kt < NT; kt++) {
        asm volatile("cp.async.wait_group 1;");
        __syncthreads();
        if (kt + 2 < NT) cp_tile(kt + 2, (kt + 2) % 3);

        const float* as = Asm + (kt % 3) * 4096;
        const float* ws = Wsm + (kt % 3) * 4096;

#pragma unroll
        for (int kk8 = 0; kk8 < 4; kk8++) {
            unsigned afrag[4][4];
#pragma unroll
            for (int mi = 0; mi < 4; mi++) {
                const int row = wm * 64 + mi * 16 + a_row;
                const int ch  = kk8 * 2 + a_cbit;
                const unsigned sa = (unsigned)__cvta_generic_to_shared(
                    as + row * 32 + ((ch ^ (row & 7)) << 2));
                ldsm_x4(afrag[mi][0], afrag[mi][1], afrag[mi][2], afrag[mi][3], sa);
            }
            unsigned bfrag[8][2];
#pragma unroll
            for (int nj2 = 0; nj2 < 4; nj2++) {
                const int row = wn * 64 + nj2 * 16 + b_row;
                const int ch  = kk8 * 2 + b_cbit;
                const unsigned sb = (unsigned)__cvta_generic_to_shared(
                    ws + row * 32 + ((ch ^ (row & 7)) << 2));
                ldsm_x4(bfrag[nj2 * 2][0], bfrag[nj2 * 2][1],
                        bfrag[nj2 * 2 + 1][0], bfrag[nj2 * 2 + 1][1], sb);
            }
#pragma unroll
            for (int mi = 0; mi < 4; mi++)
#pragma unroll
                for (int nj = 0; nj < 8; nj++)
                    mma_tf32(acc[mi][nj], afrag[mi], bfrag[nj]);
        }
        __syncthreads();
    }

    // epilogue
#pragma unroll
    for (int mi = 0; mi < 4; mi++) {
        const int r_top = bm + wm * 64 + mi * 16 + gid;
        const int r_bot = r_top + 8;
#pragma unroll
        for (int nj = 0; nj < 8; nj++) {
            const int c = bn + wn * 64 + nj * 8 + 2 * tig;
            if (MODE == 0) {
#pragma unroll
                for (int q = 0; q < 4; q++) {
                    const int row = (q < 2) ? r_top : r_bot;
                    const int col = c + (q & 1);
                    const int b = row >> 11;
                    const int n = row & 2047;
                    const int s = col % 3;
                    const int h = col / 192;
                    const int d = (col % 192) / 3;
                    const float val = f2tf32(acc[mi][nj][q] + bias[col]);
                    float* dst = (s == 0) ? g_q : (s == 1) ? g_k : g_v;
                    dst[(((size_t)(b * Hh + h)) * Nseq + n) * Dh + d] = val;
                }
            } else {
                const float2 bv = *(const float2*)(bias + c);
                float2 v0, v1;
                v0.x = acc[mi][nj][0] + bv.x; v0.y = acc[mi][nj][1] + bv.y;
                v1.x = acc[mi][nj][2] + bv.x; v1.y = acc[mi][nj][3] + bv.y;
                *(float2*)(out + (size_t)r_top * Emb + c) = v0;
                *(float2*)(out + (size_t)r_bot * Emb + c) = v1;
            }
        }
    }
}

// ---------------------------------------------------------------------------
// Flash attention, TF32 mma, register-resident online softmax.
// grid = (N/64, B*H), 128 threads = 4 warps. BR=64, BC=32, D=64.
// Double-buffered K/V smem -> single __syncthreads per tile.
// Dynamic smem: (4224 + 2*2112 + 2*2112 + 2112) floats = 59136 B.
// ---------------------------------------------------------------------------
__global__ void __launch_bounds__(128, 2) flash_kernel()
{
    extern __shared__ float fsm[];
    float* Qs = fsm;            // A-chunks (m 0..3, kg 0..7): 4224
    float* Ks = fsm + 4224;     // 2 bufs x B-chunks (nb 0..3, kg 0..7): 2112 each
    float* Vs = fsm + 8448;     // 2 bufs x B-chunks (nb 0..7, kg 0..3): 2112 each
    float* Ss = fsm + 12672;    // A-chunks per warp: 2112

    const int tid  = threadIdx.x;
    const int lane = tid & 31;
    const int w    = tid >> 5;
    const int gid  = lane >> 2;
    const int tig  = lane & 3;

    const int qb = (gridDim.x - 1) - blockIdx.x;   // heaviest blocks first
    const int bh = blockIdx.y;

    const float* Qg = g_q + ((size_t)bh * Nseq + qb * 64) * Dh;
    const float* Kg = g_k + (size_t)bh * Nseq * Dh;
    const float* Vg = g_v + (size_t)bh * Nseq * Dh;

    const float scale = 0.125f;   // exact on tf32 values (exponent-only)

    // Load & pre-scale Q tile (64x64) into A-chunk layout
#pragma unroll
    for (int i = 0; i < 8; i++) {
        const int idx = tid + i * 128;
        const int r = idx >> 4, c4 = (idx & 15) * 4;
        float4 q = *(const float4*)(Qg + r * Dh + c4);
        const int m = r >> 4, gidl = r & 7, half = (r >> 3) & 1;
        const int kg = c4 >> 3, kh = (c4 >> 2) & 1;
        float* qp = Qs + (m * 8 + kg) * 132 + half + 2 * kh;
        const float v[4] = {q.x * scale, q.y * scale, q.z * scale, q.w * scale};
#pragma unroll
        for (int u = 0; u < 4; u++) qp[(gidl * 4 + u) * 4] = v[u];
    }

    float m_top = -INFINITY, m_bot = -INFINITY;
    float l_top = 0.f, l_bot = 0.f;

    float oacc[8][4];
#pragma unroll
    for (int nj = 0; nj < 8; nj++)
#pragma unroll
        for (int q = 0; q < 4; q++) oacc[nj][q] = 0.f;

    float4 kS[4], vS[4];  // staging
    auto ldg_kv = [&](int j) {
        const float* Kt = Kg + (size_t)j * 32 * Dh;
        const float* Vt = Vg + (size_t)j * 32 * Dh;
#pragma unroll
        for (int i = 0; i < 4; i++) {
            const int idx = tid + i * 128;
            const int r = idx >> 4, c4 = (idx & 15) * 4;
            kS[i] = *(const float4*)(Kt + r * Dh + c4);
            vS[i] = *(const float4*)(Vt + r * Dh + c4);
        }
    };

    const int ntiles = 2 * qb + 2;
    ldg_kv(0);
    for (int j = 0; j < ntiles; j++) {
        float* kb = Ks + (j & 1) * 2112;
        float* vb = Vs + (j & 1) * 2112;
        // store K/V tiles into B-chunk layouts (already tf32)
#pragma unroll
        for (int i = 0; i < 4; i++) {
            const int idx = tid + i * 128;
            const int r = idx >> 4, c4 = (idx & 15) * 4;
            {   // K: (seqrow r, col d) -> chunk(nb=r/8, kg=d/8)
                const int nb = r >> 3, gidb = r & 7;
                const int kg = c4 >> 3, kh = (c4 >> 2) & 1;
                float* kp = kb + (nb * 8 + kg) * 66 + kh;
                const float v[4] = {kS[i].x, kS[i].y, kS[i].z, kS[i].w};
#pragma unroll
                for (int u = 0; u < 4; u++) kp[(gidb * 4 + u) * 2] = v[u];
            }
            {   // V: (seqrow r = k-dim, col d = n-dim) -> chunk(nb=d/8, kg=r/8)
                const int nb = c4 >> 3;
                const int kg = r >> 3, kh = (r >> 2) & 1, tv = r & 3;
                float* vp = vb + (nb * 4 + kg) * 66 + kh;
                const float v[4] = {vS[i].x, vS[i].y, vS[i].z, vS[i].w};
#pragma unroll
                for (int u = 0; u < 4; u++)
                    vp[(((c4 & 7) + u) * 4 + tv) * 2] = v[u];
            }
        }
        __syncthreads();
        if (j + 1 < ntiles) ldg_kv(j + 1);

        // ---- S = Qs * Ks^T ----
        float sacc[4][4];
#pragma unroll
        for (int nb = 0; nb < 4; nb++)
#pragma unroll
            for (int q = 0; q < 4; q++) sacc[nb][q] = 0.f;

#pragma unroll
        for (int kg = 0; kg < 8; kg++) {
            const float4 av = *(const float4*)(Qs + (w * 8 + kg) * 132 + lane * 4);
            unsigned af[4];
            af[0] = __float_as_uint(av.x); af[1] = __float_as_uint(av.y);
            af[2] = __float_as_uint(av.z); af[3] = __float_as_uint(av.w);
#pragma unroll
            for (int nb = 0; nb < 4; nb++) {
                const float2 bv = *(const float2*)(kb + (nb * 8 + kg) * 66 + lane * 2);
                unsigned bf[2];
                bf[0] = __float_as_uint(bv.x); bf[1] = __float_as_uint(bv.y);
                mma_tf32(sacc[nb], af, bf);
            }
        }

        // causal mask
        if (j >= 2 * qb) {
            const int r0g = qb * 64 + w * 16 + gid;
            const int r1g = r0g + 8;
#pragma unroll
            for (int nb = 0; nb < 4; nb++) {
                const int cg = j * 32 + nb * 8 + 2 * tig;
                if (cg     > r0g) sacc[nb][0] = -INFINITY;
                if (cg + 1 > r0g) sacc[nb][1] = -INFINITY;
                if (cg     > r1g) sacc[nb][2] = -INFINITY;
                if (cg + 1 > r1g) sacc[nb][3] = -INFINITY;
            }
        }

        // ---- online softmax (quad shuffles) ----
        float mt_t = m_top, mt_b = m_bot;
#pragma unroll
        for (int nb = 0; nb < 4; nb++) {
            mt_t = fmaxf(mt_t, fmaxf(sacc[nb][0], sacc[nb][1]));
            mt_b = fmaxf(mt_b, fmaxf(sacc[nb][2], sacc[nb][3]));
        }
        mt_t = fmaxf(mt_t, __shfl_xor_sync(0xffffffffu, mt_t, 1));
        mt_t = fmaxf(mt_t, __shfl_xor_sync(0xffffffffu, mt_t, 2));
        mt_b = fmaxf(mt_b, __shfl_xor_sync(0xffffffffu, mt_b, 1));
        mt_b = fmaxf(mt_b, __shfl_xor_sync(0xffffffffu, mt_b, 2));

        const bool nochange = (mt_t == m_top) && (mt_b == m_bot);
        const float sc_t = nochange ? 1.f : __expf(m_top - mt_t);
        const float sc_b = nochange ? 1.f : __expf(m_bot - mt_b);
        float ps_t = 0.f, ps_b = 0.f;

        float* sbase = Ss + w * 4 * 132;
#pragma unroll
        for (int nb = 0; nb < 4; nb++) {
            float p[4];
            p[0] = __expf(sacc[nb][0] - mt_t);
            p[1] = __expf(sacc[nb][1] - mt_t);
            p[2] = __expf(sacc[nb][2] - mt_b);
            p[3] = __expf(sacc[nb][3] - mt_b);
            ps_t += p[0] + p[1];
            ps_b += p[2] + p[3];
#pragma unroll
            for (int q = 0; q < 4; q++) {
                const int par  = q & 1;
                const int half = q >> 1;
                const int kin  = 2 * tig + par;
                const int tigA = kin & 3;
                const int khA  = kin >> 2;
                sbase[nb * 132 + (gid * 4 + tigA) * 4 + half + 2 * khA] = f2tf32(p[q]);
            }
        }
        ps_t += __shfl_xor_sync(0xffffffffu, ps_t, 1);
        ps_t += __shfl_xor_sync(0xffffffffu, ps_t, 2);
        ps_b += __shfl_xor_sync(0xffffffffu, ps_b, 1);
        ps_b += __shfl_xor_sync(0xffffffffu, ps_b, 2);

        l_top = l_top * sc_t + ps_t;  m_top = mt_t;
        l_bot = l_bot * sc_b + ps_b;  m_bot = mt_b;

        __syncwarp();

        // ---- O = O*rescale + P*V (skip rescale when max unchanged warp-wide) ----
        if (!__all_sync(0xffffffffu, nochange)) {
#pragma unroll
            for (int nj = 0; nj < 8; nj++) {
                oacc[nj][0] *= sc_t; oacc[nj][1] *= sc_t;
                oacc[nj][2] *= sc_b; oacc[nj][3] *= sc_b;
            }
        }
#pragma unroll
        for (int kg = 0; kg < 4; kg++) {
            const float4 av = *(const float4*)(sbase + kg * 132 + lane * 4);
            unsigned af[4];
            af[0] = __float_as_uint(av.x); af[1] = __float_as_uint(av.y);
            af[2] = __float_as_uint(av.z); af[3] = __float_as_uint(av.w);
#pragma unroll
            for (int nb = 0; nb < 8; nb++) {
                const float2 bv = *(const float2*)(vb + (nb * 4 + kg) * 66 + lane * 2);
                unsigned bf[2];
                bf[0] = __float_as_uint(bv.x); bf[1] = __float_as_uint(bv.y);
                mma_tf32(oacc[nb], af, bf);
            }
        }
        // no end-of-loop sync: next iteration writes the other K/V buffer
    }

    const int b = bh >> 4, h = bh & 15;
    const float inv_top = 1.f / l_top;
    const float inv_bot = 1.f / l_bot;
    const int n_top = qb * 64 + w * 16 + gid;
    const int n_bot = n_top + 8;
#pragma unroll
    for (int nj = 0; nj < 8; nj++) {
        const int c = nj * 8 + 2 * tig;
        float2 v0, v1;
        v0.x = f2tf32(oacc[nj][0] * inv_top); v0.y = f2tf32(oacc[nj][1] * inv_top);
        v1.x = f2tf32(oacc[nj][2] * inv_bot); v1.y = f2tf32(oacc[nj][3] * inv_bot);
        *(float2*)(g_ao + ((size_t)(b * Nseq + n_top)) * (Hh * Dh) + h * Dh + c) = v0;
        *(float2*)(g_ao + ((size_t)(b * Nseq + n_bot)) * (Hh * Dh) + h * Dh + c) = v1;
    }
}

// ---------------------------------------------------------------------------
extern "C" void kernel_launch(void* const* d_in, const int* in_sizes, int n_in,
                              void* d_out, int out_size)
{
    const float* x    = (const float*)d_in[0];
    const float* Wqkv = (const float*)d_in[1];
    const float* bqkv = (const float*)d_in[2];
    const float* Wout = (const float*)d_in[3];
    const float* bout = (const float*)d_in[4];
    float* out = (float*)d_out;

    // raise dynamic smem limits (idempotent)
    cudaFuncSetAttribute(gemm_tf32_kernel<0>, cudaFuncAttributeMaxDynamicSharedMemorySize, 98304);
    cudaFuncSetAttribute(gemm_tf32_kernel<1>, cudaFuncAttributeMaxDynamicSharedMemorySize, 98304);
    cudaFuncSetAttribute(flash_kernel, cudaFuncAttributeMaxDynamicSharedMemorySize, 59136);

    float *gx, *gwq, *gwo;
    cudaGetSymbolAddress((void**)&gx,  g_x);
    cudaGetSymbolAddress((void**)&gwq, g_wq);
    cudaGetSymbolAddress((void**)&gwo, g_wo);

    // K0: tf32 pre-conversion of x, Wqkv, Wout
    cvt_tf32_kernel<<<(Bsz * Nseq * Emb / 4 + 255) / 256, 256>>>((const float4*)x,    (float4*)gx,  Bsz * Nseq * Emb / 4);
    cvt_tf32_kernel<<<(3 * Hh * Dh * Emb / 4 + 255) / 256, 256>>>((const float4*)Wqkv, (float4*)gwq, 3 * Hh * Dh * Emb / 4);
    cvt_tf32_kernel<<<(Emb * Hh * Dh / 4 + 255) / 256, 256>>>((const float4*)Wout,  (float4*)gwo, Emb * Hh * Dh / 4);

    // K1: QKV projection + de-interleave scatter. C is [4096, 3072].
    gemm_tf32_kernel<0><<<dim3(3072 / 128, 4096 / 128), 128, 98304>>>(bqkv, nullptr);

    // K2: causal flash attention. grid (N/64, B*H).
    flash_kernel<<<dim3(Nseq / 64, Bsz * Hh), 128, 59136>>>();

    // K3: output projection. C is [4096, 1024].
    gemm_tf32_kernel<1><<<dim3(1024 / 128, 4096 / 128), 128, 98304>>>(bout, out);
}